// round 14
// baseline (speedup 1.0000x reference)
#include <cuda_runtime.h>
#include <cuda_fp16.h>
#include <cstdint>

#define B_  8
#define C_  256
#define N_  4096
#define CQ_ 32
#define TQ  128
#define TJ  64
#define NT  (N_ / TJ)

#define LOG2E 1.4426950408889634f

// ---------------- gmem scratch: MMA-ready lds128 tile layouts ----------------
__device__ __align__(128) __half g_q[8 * 32 * 8192];
__device__ __align__(128) __half g_k[8 * 64 * 4096];
__device__ __align__(128) __half g_v[8 * 64 * 16384];
// W A-fragments: hi = uint4[0..10239], lo = uint4[10240..20479]
__device__ __align__(128) __half g_wA[2 * 20 * 16 * 32 * 8];

// ---------------- PTX helpers ----------------
__device__ __forceinline__ uint32_t su32(const void* p) {
    uint32_t a;
    asm("{ .reg .u64 t; cvta.to.shared.u64 t, %1; cvt.u32.u64 %0, t; }" : "=r"(a) : "l"(p));
    return a;
}
__device__ __forceinline__ float ex2f(float x) {
    float y;
    asm("ex2.approx.ftz.f32 %0, %1;" : "=f"(y) : "f"(x));
    return y;
}
__device__ __forceinline__ void lds128(uint32_t& a, uint32_t& b, uint32_t& c, uint32_t& d,
                                       uint32_t addr) {
    asm volatile("ld.shared.v4.b32 {%0, %1, %2, %3}, [%4];"
                 : "=r"(a), "=r"(b), "=r"(c), "=r"(d) : "r"(addr));
}
__device__ __forceinline__ void sts128(uint32_t addr, uint32_t a, uint32_t b,
                                       uint32_t c, uint32_t d) {
    asm volatile("st.shared.v4.b32 [%0], {%1, %2, %3, %4};"
                 :: "r"(addr), "r"(a), "r"(b), "r"(c), "r"(d) : "memory");
}
__device__ __forceinline__ void sts_f2(uint32_t addr, float a, float b) {
    asm volatile("st.shared.v2.f32 [%0], {%1, %2};" :: "r"(addr), "f"(a), "f"(b) : "memory");
}
__device__ __forceinline__ void lds_f2(float& a, float& b, uint32_t addr) {
    asm volatile("ld.shared.v2.f32 {%0, %1}, [%2];" : "=f"(a), "=f"(b) : "r"(addr));
}
__device__ __forceinline__ void mma_f16(float* c, uint32_t a0, uint32_t a1,
                                        uint32_t a2, uint32_t a3,
                                        uint32_t b0, uint32_t b1) {
    asm volatile(
        "mma.sync.aligned.m16n8k16.row.col.f32.f16.f16.f32 "
        "{%0,%1,%2,%3}, {%4,%5,%6,%7}, {%8,%9}, {%0,%1,%2,%3};"
        : "+f"(c[0]), "+f"(c[1]), "+f"(c[2]), "+f"(c[3])
        : "r"(a0), "r"(a1), "r"(a2), "r"(a3), "r"(b0), "r"(b1));
}
__device__ __forceinline__ uint32_t packh2(float hi, float lo) {
    uint32_t u;
    asm("cvt.rn.f16x2.f32 %0, %1, %2;" : "=r"(u) : "f"(hi), "f"(lo));
    return u;
}
__device__ __forceinline__ uint32_t pack2h(__half hi, __half lo) {
    return ((uint32_t)__half_as_ushort(hi) << 16) | __half_as_ushort(lo);
}
__device__ __forceinline__ float h2sum(uint32_t u) {
    float lo, hi;
    asm("{.reg .b16 l, h;\n mov.b32 {l, h}, %2;\n cvt.f32.f16 %0, l;\n cvt.f32.f16 %1, h;}"
        : "=f"(lo), "=f"(hi) : "r"(u));
    return lo + hi;
}
__device__ __forceinline__ void cpa16(uint32_t dst, const void* src) {
    asm volatile("cp.async.cg.shared.global [%0], [%1], 16;" :: "r"(dst), "l"(src));
}
#define CP_COMMIT() asm volatile("cp.async.commit_group;" ::: "memory")
#define CP_WAIT1()  asm volatile("cp.async.wait_group 1;" ::: "memory")
#define MB_INIT(mb, cnt) \
    asm volatile("mbarrier.init.shared.b64 [%0], %1;" :: "r"(mb), "r"(cnt) : "memory")
#define MB_EXPECT(mb, tx) \
    asm volatile("mbarrier.arrive.expect_tx.shared.b64 _, [%0], %1;" :: "r"(mb), "r"(tx) : "memory")
#define MB_ARRIVE(mb) \
    asm volatile("mbarrier.arrive.shared.b64 _, [%0];" :: "r"(mb) : "memory")
__device__ __forceinline__ void mb_wait(uint32_t mb, uint32_t parity) {
    asm volatile(
        "{\n .reg .pred P;\n"
        "W%=:\n"
        " mbarrier.try_wait.parity.acquire.cta.shared::cta.b64 P, [%0], %1, 0x989680;\n"
        " @P bra D%=;\n"
        " bra W%=;\n"
        "D%=:\n}"
        :: "r"(mb), "r"(parity) : "memory");
}
__device__ __forceinline__ void bulkcp(uint32_t dst, const void* src, uint32_t bytes, uint32_t mbar) {
    asm volatile(
        "cp.async.bulk.shared::cluster.global.mbarrier::complete_tx::bytes [%0], [%1], %2, [%3];"
        :: "r"(dst), "l"(src), "r"(bytes), "r"(mbar) : "memory");
}
#define BAR_PAIR(id) \
    asm volatile("bar.sync %0, 64;" :: "r"(id) : "memory")

// ====================================================================
// W prep (unchanged from round 13).
// ====================================================================
__global__ void __launch_bounds__(512) wprep(
    const float* __restrict__ wv, const float* __restrict__ wq,
    const float* __restrict__ wk)
{
    const int dt = blockIdx.x;
    const int tid = threadIdx.x;
    const int kc = tid >> 5, ln = tid & 31;
    const int l4 = ln >> 2, t = ln & 3;

    const float* W;
    int rbase;
    float scale = 1.0f;
    if (dt < 16)      { W = wv; rbase = dt * 16; }
    else if (dt < 18) { W = wq; rbase = (dt - 16) * 16; scale = LOG2E; }
    else              { W = wk; rbase = (dt - 18) * 16; }

    const int r0 = rbase + l4, r1 = r0 + 8;
    const int c0 = kc * 16 + 2 * t;
    float f[8];
    f[0] = W[r0 * 256 + c0]     * scale;  f[1] = W[r0 * 256 + c0 + 1] * scale;
    f[2] = W[r1 * 256 + c0]     * scale;  f[3] = W[r1 * 256 + c0 + 1] * scale;
    f[4] = W[r0 * 256 + c0 + 8] * scale;  f[5] = W[r0 * 256 + c0 + 9] * scale;
    f[6] = W[r1 * 256 + c0 + 8] * scale;  f[7] = W[r1 * 256 + c0 + 9] * scale;

    __half h[8]; float l[8];
#pragma unroll
    for (int i = 0; i < 8; i++) {
        h[i] = __float2half_rn(f[i]);
        l[i] = f[i] - __half2float(h[i]);
    }
    uint4 hiw, low;
    hiw.x = pack2h(h[1], h[0]); hiw.y = pack2h(h[3], h[2]);
    hiw.z = pack2h(h[5], h[4]); hiw.w = pack2h(h[7], h[6]);
    low.x = packh2(l[1], l[0]); low.y = packh2(l[3], l[2]);
    low.z = packh2(l[5], l[4]); low.w = packh2(l[7], l[6]);
    uint4* dst = (uint4*)g_wA + (dt * 512 + kc * 32 + ln);
    dst[0]     = hiw;
    dst[10240] = low;
}

// ====================================================================
// proj_mma v2: kc-pipelined (cp.async chunk staging, depth-2 prefetch).
// V warps: 2-pass (hi*hi + lo_w*hi_x); Q/K warps: 3-pass.
// SMEM: raw chunks 4 x 1088 floats @0 ; frag 2 x 1024 floats @4352 ;
//       scatter staging reuses @0 after final sync.
// ====================================================================
#define RAWF  1088
#define FRAG0 4352
#define PROJ2_SMEM_BYTES (6400 * 4)

__global__ void __launch_bounds__(640, 1) proj_mma(
    const float* __restrict__ x,
    const float* __restrict__ bq, const float* __restrict__ bk,
    const float* __restrict__ bv)
{
    extern __shared__ float sm[];
    const uint32_t sb = su32(sm);
    const int tid = threadIdx.x;
    const int b  = blockIdx.y;
    const int bx = blockIdx.x;
    const int w  = tid >> 5, l = tid & 31;
    const int l4 = l >> 2, t = l & 3;

    const float* xbase = x + ((size_t)b * C_) * N_ + bx * 64;

    // stage one 16-channel chunk via cp.async (threads 0..255)
    auto stage = [&](int chunk) {
        if (tid < 256) {
            int r = tid >> 4, g = tid & 15;
            uint32_t dst = sb + (uint32_t)(((chunk & 3) * RAWF + r * 68 + g * 4) * 4);
            cpa16(dst, xbase + (size_t)(chunk * 16 + r) * N_ + g * 4);
        }
        CP_COMMIT();
    };

    stage(0);
    stage(1);

    float acc[8][4];
#pragma unroll
    for (int i = 0; i < 8; i++)
#pragma unroll
        for (int e = 0; e < 4; e++) acc[i][e] = 0.f;

    const uint4* wAhi = (const uint4*)g_wA + (w * 512 + l);

    for (int kc = 0; kc < 16; kc++) {
        CP_WAIT1();            // chunk kc resident (kc+1 may be in flight)
        __syncthreads();       // frag slot (kc&1) free (MMA kc-2 done everywhere)

        // ---- convert chunk kc -> frag slot kc&1 (threads 0..255) ----
        if (tid < 256) {
            int ln = tid & 31, nf = tid >> 5;
            int l4p = ln >> 2, tp = ln & 3;
            int n = nf * 8 + l4p;
            const float* rp = sm + (kc & 3) * RAWF + n;
            float f0 = rp[(2 * tp) * 68];
            float f1 = rp[(2 * tp + 1) * 68];
            float f2 = rp[(2 * tp + 8) * 68];
            float f3 = rp[(2 * tp + 9) * 68];
            __half h0 = __float2half_rn(f0), h1 = __float2half_rn(f1);
            __half h2 = __float2half_rn(f2), h3 = __float2half_rn(f3);
            uint4 o;
            o.x = pack2h(h1, h0);
            o.y = pack2h(h3, h2);
            o.z = packh2(f1 - __half2float(h1), f0 - __half2float(h0));
            o.w = packh2(f3 - __half2float(h3), f2 - __half2float(h2));
            *(uint4*)(sm + FRAG0 + (((kc & 1) * 256 + nf * 32 + ln) * 4)) = o;
        }
        __syncthreads();       // frags visible to all warps

        if (kc + 2 < 16) stage(kc + 2);

        // ---- MMA for chunk kc ----
        uint4 ah = __ldg(wAhi + kc * 32);
        uint4 al = __ldg(wAhi + kc * 32 + 10240);
        const uint4* fb = (const uint4*)(sm + FRAG0) + (kc & 1) * 256 + l;
#pragma unroll
        for (int nf = 0; nf < 8; nf++) {
            uint4 xb = fb[nf * 32];
            mma_f16(acc[nf], ah.x, ah.y, ah.z, ah.w, xb.x, xb.y);
            mma_f16(acc[nf], al.x, al.y, al.z, al.w, xb.x, xb.y);
            if (w >= 16)       // Q/K keep 3rd pass; V skips (stored fp16 anyway)
                mma_f16(acc[nf], ah.x, ah.y, ah.z, ah.w, xb.z, xb.w);
        }
    }
    __syncthreads();           // smem reuse for scatter staging

    // ---- scatter to attn layouts (verbatim from round 13) ----
    if (w < 16) {
        const float bv0 = __ldg(bv + w * 16 + l4);
        const float bv1 = __ldg(bv + w * 16 + l4 + 8);
        __half* vout = g_v + (((size_t)(b * 64 + bx)) << 14) + w * 256 + l4 * 32 + t * 8;
#pragma unroll
        for (int u = 0; u < 4; u++) {
            const int nA = 2 * u, nB = 2 * u + 1;
            uint4 o;
            o.x = packh2(acc[nA][1] + bv0, acc[nA][0] + bv0);
            o.y = packh2(acc[nB][1] + bv0, acc[nB][0] + bv0);
            o.z = packh2(acc[nA][3] + bv1, acc[nA][2] + bv1);
            o.w = packh2(acc[nB][3] + bv1, acc[nB][2] + bv1);
            *(uint4*)(vout + u * 4096) = o;
        }
    } else {
        float* stg = sm + (w - 16) * 1100;
#pragma unroll
        for (int nf = 0; nf < 8; nf++) {
            stg[l4 * 68 + nf * 8 + 2 * t]           = acc[nf][0];
            stg[l4 * 68 + nf * 8 + 2 * t + 1]       = acc[nf][1];
            stg[(l4 + 8) * 68 + nf * 8 + 2 * t]     = acc[nf][2];
            stg[(l4 + 8) * 68 + nf * 8 + 2 * t + 1] = acc[nf][3];
        }
        __syncwarp();
        const int kg  = (w - 16) & 1;
        const bool isQ = (w < 18);
        const float* bias = isQ ? bq : bk;
        const float bsc = isQ ? LOG2E : 1.0f;
        __half *outh, *outl;
        if (isQ) {
            outh = g_q + (((size_t)(b * 32 + (bx >> 1))) << 13) + kg * 2048;
            outl = outh + 4096;
        } else {
            outh = g_k + (((size_t)(b * 64 + bx)) << 12);
            outl = outh + 2048;
        }
#pragma unroll
        for (int i = 0; i < 8; i++) {
            const int tidx = i * 32 + l;
            const int n = tidx >> 2, tt = tidx & 3;
            const int d0 = kg * 16 + 2 * tt;
            float f0 = stg[(2 * tt) * 68 + n]     + bsc * __ldg(bias + d0);
            float f1 = stg[(2 * tt + 1) * 68 + n] + bsc * __ldg(bias + d0 + 1);
            float f2 = stg[(2 * tt + 8) * 68 + n] + bsc * __ldg(bias + d0 + 8);
            float f3 = stg[(2 * tt + 9) * 68 + n] + bsc * __ldg(bias + d0 + 9);
            __half h0 = __float2half_rn(f0), h1 = __float2half_rn(f1);
            __half h2 = __float2half_rn(f2), h3 = __float2half_rn(f3);
            uint2 hw, lw;
            hw.x = pack2h(h1, h0);
            hw.y = pack2h(h3, h2);
            lw.x = packh2(f1 - __half2float(h1), f0 - __half2float(h0));
            lw.y = packh2(f3 - __half2float(h3), f2 - __half2float(h2));
            uint32_t off;
            if (isQ) {
                const int r = (bx & 1) * 64 + n;
                off = (uint32_t)((r >> 4) * 256 + (r & 7) * 32 + tt * 8 + ((r >> 3) & 1) * 4);
            } else {
                off = (uint32_t)((n >> 3) * 256 + (n & 7) * 32 + tt * 8 + kg * 4);
            }
            *(uint2*)(outh + off) = hw;
            *(uint2*)(outl + off) = lw;
        }
    }
}

// ====================================================================
// fp16 flash attention (UNCHANGED from round 13).
// ====================================================================
#define SM_BUF   0
#define BUF_SZ   40960
#define SM_PSH   163840
#define SM_F     196608
#define SM_MX    197632
#define SM_LS    198656
#define SM_LS2   199680
#define SM_MBAR  200192
#define ATTN_SMEM_BYTES 200448

__global__ void __launch_bounds__(512, 1) attn_mma(
    const float* __restrict__ x, float* __restrict__ out)
{
    extern __shared__ float sm[];
    const uint32_t sb = su32(sm);
    const int tid = threadIdx.x;
    const int w   = tid >> 5;
    const int qw  = w & 7;
    const int cg  = w >> 3;
    const int qp  = w & 3;
    const int ch  = w >> 2;
    const int l   = tid & 31;
    const int l4  = l >> 2;
    const int t   = l & 3;
    const int b   = blockIdx.y;
    const int qt  = blockIdx.x;
    const int q0  = qt * TQ;
    const uint32_t lane16 = (uint32_t)l * 16;
    const int barid = 1 + qw;

    const uint32_t mbD = sb + SM_MBAR;
    const uint32_t mbC = sb + SM_MBAR + 32;
    const uint32_t mxO = sb + SM_MX + (uint32_t)(((qw * 2 + cg) * 8 + l4) * 8);
    const uint32_t mxP = sb + SM_MX + (uint32_t)(((qw * 2 + (1 - cg)) * 8 + l4) * 8);

    if (tid == 0) {
#pragma unroll
        for (int i = 0; i < 4; i++) { MB_INIT(mbD + 8 * i, 1); MB_INIT(mbC + 8 * i, 16); }
    }
    __syncthreads();

    if (tid == 0) {
#pragma unroll
        for (int i = 0; i < 4; i++) {
            MB_EXPECT(mbD + 8 * i, 40960);
            bulkcp(sb + SM_BUF + i * BUF_SZ,
                   (const char*)g_k + ((size_t)(b * 64 + i) << 13), 8192, mbD + 8 * i);
            bulkcp(sb + SM_BUF + i * BUF_SZ + 8192,
                   (const char*)g_v + ((size_t)(b * 64 + i) << 15), 32768, mbD + 8 * i);
        }
    }

    uint32_t qh[2][4], ql[2][4];
    {
        const __half* qgm = g_q + ((size_t)(b * 32 + qt) << 13);
#pragma unroll
        for (int kg = 0; kg < 2; kg++) {
            uint4 v = *(const uint4*)(qgm + kg * 2048 + qw * 256 + l * 8);
            qh[kg][0] = v.x; qh[kg][1] = v.z; qh[kg][2] = v.y; qh[kg][3] = v.w;
            uint4 u2 = *(const uint4*)(qgm + 4096 + kg * 2048 + qw * 256 + l * 8);
            ql[kg][0] = u2.x; ql[kg][1] = u2.z; ql[kg][2] = u2.y; ql[kg][3] = u2.w;
        }
    }

    float o[16][4];
#pragma unroll
    for (int i = 0; i < 16; i++)
#pragma unroll
        for (int e = 0; e < 4; e++) o[i][e] = 0.f;
    float m0 = -1e30f, m1 = -1e30f, ls0 = 0.f, ls1 = 0.f;

    for (int tt = 0; tt < NT; tt++) {
        const int buf = tt & 3;
        const uint32_t kb = sb + SM_BUF + (uint32_t)buf * BUF_SZ;
        const uint32_t vb = kb + 8192;
        const uint32_t par = (uint32_t)((tt >> 2) & 1);
        const uint32_t pshB = sb + SM_PSH + (uint32_t)(tt & 1) * 16384;
        const uint32_t fB   = sb + SM_F   + (uint32_t)(tt & 1) * 512;
        mb_wait(mbD + 8 * buf, par);

        float sacc[4][4];
        const uint32_t kaBase = kb + (uint32_t)(cg * 2048) + lane16;
#pragma unroll
        for (int nt = 0; nt < 4; nt++) {
#pragma unroll
            for (int e = 0; e < 4; e++) sacc[nt][e] = 0.f;
            const uint32_t ka = kaBase + (uint32_t)(nt * 512);
            uint32_t h0, h1, h2, h3, g0, g1, g2, g3;
            lds128(h0, h1, h2, h3, ka);
            lds128(g0, g1, g2, g3, ka + 4096);
            mma_f16(sacc[nt], qh[0][0], qh[0][1], qh[0][2], qh[0][3], h0, h1);
            mma_f16(sacc[nt], qh[1][0], qh[1][1], qh[1][2], qh[1][3], h2, h3);
            mma_f16(sacc[nt], ql[0][0], ql[0][1], ql[0][2], ql[0][3], h0, h1);
            mma_f16(sacc[nt], ql[1][0], ql[1][1], ql[1][2], ql[1][3], h2, h3);
            mma_f16(sacc[nt], qh[0][0], qh[0][1], qh[0][2], qh[0][3], g0, g1);
            mma_f16(sacc[nt], qh[1][0], qh[1][1], qh[1][2], qh[1][3], g2, g3);
        }
        float mh0 = sacc[0][0], mh1 = sacc[0][2];
#pragma unroll
        for (int nt = 0; nt < 4; nt++) {
            mh0 = fmaxf(mh0, fmaxf(sacc[nt][0], sacc[nt][1]));
            mh1 = fmaxf(mh1, fmaxf(sacc[nt][2], sacc[nt][3]));
        }
        mh0 = fmaxf(mh0, __shfl_xor_sync(0xffffffffu, mh0, 1));
        mh0 = fmaxf(mh0, __shfl_xor_sync(0xffffffffu, mh0, 2));
        mh1 = fmaxf(mh1, __shfl_xor_sync(0xffffffffu, mh1, 1));
        mh1 = fmaxf(mh1, __shfl_xor_sync(0xffffffffu, mh1, 2));
        if (t == 0) sts_f2(mxO, mh0, mh1);
        BAR_PAIR(barid);
        float pm0, pm1;
        lds_f2(pm0, pm1, mxP);
        const float m0n = fmaxf(m0, fmaxf(mh0, pm0));
        const float m1n = fmaxf(m1, fmaxf(mh1, pm1));
        const float f0 = ex2f(m0 - m0n);
        const float f1 = ex2f(m1 - m1n);
        m0 = m0n; m1 = m1n;
        ls0 *= f0; ls1 *= f1;
        if (cg == 0 && t == 0) sts_f2(fB + (uint32_t)(qw * 64 + l4 * 8), f0, f1);

#pragma unroll
        for (int ul = 0; ul < 2; ul++) {
            const int u = cg * 2 + ul;
            uint32_t A0, A1, A2, A3;
            {
                float p0 = ex2f(sacc[2 * ul][0] - m0), p1 = ex2f(sacc[2 * ul][1] - m0);
                float p2 = ex2f(sacc[2 * ul][2] - m1), p3 = ex2f(sacc[2 * ul][3] - m1);
                A0 = packh2(p1, p0); A1 = packh2(p3, p2);
                p0 = ex2f(sacc[2 * ul + 1][0] - m0); p1 = ex2f(sacc[2 * ul + 1][1] - m0);
                p2 = ex2f(sacc[2 * ul + 1][2] - m1); p3 = ex2f(sacc[2 * ul + 1][3] - m1);
                A2 = packh2(p1, p0); A3 = packh2(p3, p2);
                ls0 += h2sum(A0) + h2sum(A2);
                ls1 += h2sum(A1) + h2sum(A3);
            }
            sts128(pshB + (uint32_t)(qw * 2048 + u * 512) + lane16, A0, A1, A2, A3);
        }
        __syncthreads();

        {
            float g0a, g1a, g0b, g1b;
            lds_f2(g0a, g1a, fB + (uint32_t)((2 * qp) * 64 + l4 * 8));
            lds_f2(g0b, g1b, fB + (uint32_t)((2 * qp + 1) * 64 + l4 * 8));
#pragma unroll
            for (int i = 0; i < 8; i++) {
                o[i][0] *= g0a; o[i][1] *= g0a; o[i][2] *= g1a; o[i][3] *= g1a;
            }
#pragma unroll
            for (int i = 8; i < 16; i++) {
                o[i][0] *= g0b; o[i][1] *= g0b; o[i][2] *= g1b; o[i][3] *= g1b;
            }
        }
#pragma unroll
        for (int u = 0; u < 4; u++) {
            uint32_t A0, A1, A2, A3, B0, B1, B2, B3;
            lds128(A0, A1, A2, A3, pshB + (uint32_t)((2 * qp) * 2048 + u * 512) + lane16);
            lds128(B0, B1, B2, B3, pshB + (uint32_t)((2 * qp + 1) * 2048 + u * 512) + lane16);
            uint32_t va = vb + (uint32_t)(u * 8192 + ch * 2048) + lane16;
#pragma unroll
            for (int p = 0; p < 4; p++) {
                uint32_t v0, v1, v2, v3;
                lds128(v0, v1, v2, v3, va);
                mma_f16(o[p * 2],         A0, A1, A2, A3, v0, v1);
                mma_f16(o[p * 2 + 1],     A0, A1, A2, A3, v2, v3);
                mma_f16(o[8 + p * 2],     B0, B1, B2, B3, v0, v1);
                mma_f16(o[8 + p * 2 + 1], B0, B1, B2, B3, v2, v3);
                va += 512;
            }
        }
        if (l == 0) MB_ARRIVE(mbC + 8 * buf);
        if (tid == 0 && tt + 4 < NT) {
            mb_wait(mbC + 8 * buf, par);
            MB_EXPECT(mbD + 8 * buf, 40960);
            bulkcp(kb, (const char*)g_k + ((size_t)(b * 64 + tt + 4) << 13), 8192, mbD + 8 * buf);
            bulkcp(vb, (const char*)g_v + ((size_t)(b * 64 + tt + 4) << 15), 32768, mbD + 8 * buf);
        }
    }

    ls0 += __shfl_xor_sync(0xffffffffu, ls0, 1);
    ls0 += __shfl_xor_sync(0xffffffffu, ls0, 2);
    ls1 += __shfl_xor_sync(0xffffffffu, ls1, 1);
    ls1 += __shfl_xor_sync(0xffffffffu, ls1, 2);
    if (t == 0) sts_f2(sb + SM_LS + (uint32_t)(((qw * 2 + cg) * 8 + l4) * 8), ls0, ls1);
    __syncthreads();
    {
        float p0, p1;
        lds_f2(p0, p1, sb + SM_LS + (uint32_t)(((qw * 2 + (1 - cg)) * 8 + l4) * 8));
        ls0 += p0; ls1 += p1;
    }
    if (cg == 0 && t == 0) {
        sm[(SM_LS2 >> 2) + qw * 16 + l4]     = ls0;
        sm[(SM_LS2 >> 2) + qw * 16 + l4 + 8] = ls1;
    }
    __syncthreads();
    float inv0a, inv1a, inv0b, inv1b;
    {
        const float* lsf = sm + (SM_LS2 >> 2);
        inv0a = 1.0f / lsf[(2 * qp) * 16 + l4];
        inv1a = 1.0f / lsf[(2 * qp) * 16 + l4 + 8];
        inv0b = 1.0f / lsf[(2 * qp + 1) * 16 + l4];
        inv1b = 1.0f / lsf[(2 * qp + 1) * 16 + l4 + 8];
    }

    float* stage = sm;
#pragma unroll 1
    for (int ch2 = 0; ch2 < 4; ch2++) {
        __syncthreads();
        if (ch == ch2) {
#pragma unroll
            for (int qb = 0; qb < 2; qb++) {
                const int q = (2 * qp + qb) * 16 + l4;
                const float i0 = qb ? inv0b : inv0a;
                const float i1 = qb ? inv1b : inv1a;
#pragma unroll
                for (int k = 0; k < 8; k++) {
                    const int i = qb * 8 + k;
                    const int cloc = k * 8 + 2 * t;
                    stage[cloc * 132 + q]           = o[i][0] * i0;
                    stage[(cloc + 1) * 132 + q]     = o[i][1] * i0;
                    stage[cloc * 132 + q + 8]       = o[i][2] * i1;
                    stage[(cloc + 1) * 132 + q + 8] = o[i][3] * i1;
                }
            }
        }
        __syncthreads();
        const int cloc2 = tid & 63;
        const int seg   = tid >> 6;
        const int cglob = ch2 * 64 + cloc2;
        const size_t gbase = ((size_t)(b * C_ + cglob)) * N_ + q0 + seg * 16;
        const float4* xs4 = (const float4*)(x + gbase);
        float4* os4 = (float4*)(out + gbase);
        const float* srow = stage + cloc2 * 132 + seg * 16;
#pragma unroll
        for (int i = 0; i < 4; i++) {
            float4 v = *(const float4*)(srow + 4 * i);
            float4 xv = xs4[i];
            float4 r;
            r.x = xv.x + v.x; r.y = xv.y + v.y; r.z = xv.z + v.z; r.w = xv.w + v.w;
            os4[i] = r;
        }
    }
}

// ====================================================================
extern "C" void kernel_launch(void* const* d_in, const int* in_sizes, int n_in,
                              void* d_out, int out_size)
{
    const float* x  = (const float*)d_in[0];
    const float* wq = (const float*)d_in[1];
    const float* bq = (const float*)d_in[2];
    const float* wk = (const float*)d_in[3];
    const float* bk = (const float*)d_in[4];
    const float* wv = (const float*)d_in[5];
    const float* bv = (const float*)d_in[6];
    float* out = (float*)d_out;

    cudaFuncSetAttribute(proj_mma, cudaFuncAttributeMaxDynamicSharedMemorySize, PROJ2_SMEM_BYTES);
    cudaFuncSetAttribute(attn_mma, cudaFuncAttributeMaxDynamicSharedMemorySize, ATTN_SMEM_BYTES);

    wprep<<<20, 512>>>(wv, wq, wk);
    proj_mma<<<dim3(64, 8), 640, PROJ2_SMEM_BYTES>>>(x, bq, bk, bv);
    attn_mma<<<dim3(N_ / TQ, B_), 512, ATTN_SMEM_BYTES>>>(x, out);
}

// round 15
// speedup vs baseline: 1.0302x; 1.0302x over previous
#include <cuda_runtime.h>
#include <cuda_fp16.h>
#include <cstdint>

#define B_  8
#define C_  256
#define N_  4096
#define CQ_ 32
#define TQ  128
#define TJ  64
#define NT  (N_ / TJ)

#define LOG2E 1.4426950408889634f

// ---------------- gmem scratch: MMA-ready lds128 tile layouts ----------------
__device__ __align__(128) __half g_q[8 * 32 * 8192];
__device__ __align__(128) __half g_k[8 * 64 * 4096];
__device__ __align__(128) __half g_v[8 * 64 * 16384];
// W A-fragments: hi = uint4[0..10239], lo = uint4[10240..20479]
__device__ __align__(128) __half g_wA[2 * 20 * 16 * 32 * 8];

// ---------------- PTX helpers ----------------
__device__ __forceinline__ uint32_t su32(const void* p) {
    uint32_t a;
    asm("{ .reg .u64 t; cvta.to.shared.u64 t, %1; cvt.u32.u64 %0, t; }" : "=r"(a) : "l"(p));
    return a;
}
__device__ __forceinline__ float ex2f(float x) {
    float y;
    asm("ex2.approx.ftz.f32 %0, %1;" : "=f"(y) : "f"(x));
    return y;
}
__device__ __forceinline__ void lds128(uint32_t& a, uint32_t& b, uint32_t& c, uint32_t& d,
                                       uint32_t addr) {
    asm volatile("ld.shared.v4.b32 {%0, %1, %2, %3}, [%4];"
                 : "=r"(a), "=r"(b), "=r"(c), "=r"(d) : "r"(addr));
}
__device__ __forceinline__ void sts128(uint32_t addr, uint32_t a, uint32_t b,
                                       uint32_t c, uint32_t d) {
    asm volatile("st.shared.v4.b32 [%0], {%1, %2, %3, %4};"
                 :: "r"(addr), "r"(a), "r"(b), "r"(c), "r"(d) : "memory");
}
__device__ __forceinline__ void sts_f2(uint32_t addr, float a, float b) {
    asm volatile("st.shared.v2.f32 [%0], {%1, %2};" :: "r"(addr), "f"(a), "f"(b) : "memory");
}
__device__ __forceinline__ void lds_f2(float& a, float& b, uint32_t addr) {
    asm volatile("ld.shared.v2.f32 {%0, %1}, [%2];" : "=f"(a), "=f"(b) : "r"(addr));
}
__device__ __forceinline__ void mma_f16(float* c, uint32_t a0, uint32_t a1,
                                        uint32_t a2, uint32_t a3,
                                        uint32_t b0, uint32_t b1) {
    asm volatile(
        "mma.sync.aligned.m16n8k16.row.col.f32.f16.f16.f32 "
        "{%0,%1,%2,%3}, {%4,%5,%6,%7}, {%8,%9}, {%0,%1,%2,%3};"
        : "+f"(c[0]), "+f"(c[1]), "+f"(c[2]), "+f"(c[3])
        : "r"(a0), "r"(a1), "r"(a2), "r"(a3), "r"(b0), "r"(b1));
}
__device__ __forceinline__ uint32_t packh2(float hi, float lo) {
    uint32_t u;
    asm("cvt.rn.f16x2.f32 %0, %1, %2;" : "=r"(u) : "f"(hi), "f"(lo));
    return u;
}
__device__ __forceinline__ uint32_t pack2h(__half hi, __half lo) {
    return ((uint32_t)__half_as_ushort(hi) << 16) | __half_as_ushort(lo);
}
__device__ __forceinline__ float h2sum(uint32_t u) {
    float lo, hi;
    asm("{.reg .b16 l, h;\n mov.b32 {l, h}, %2;\n cvt.f32.f16 %0, l;\n cvt.f32.f16 %1, h;}"
        : "=f"(lo), "=f"(hi) : "r"(u));
    return lo + hi;
}
#define MB_INIT(mb, cnt) \
    asm volatile("mbarrier.init.shared.b64 [%0], %1;" :: "r"(mb), "r"(cnt) : "memory")
#define MB_EXPECT(mb, tx) \
    asm volatile("mbarrier.arrive.expect_tx.shared.b64 _, [%0], %1;" :: "r"(mb), "r"(tx) : "memory")
#define MB_ARRIVE(mb) \
    asm volatile("mbarrier.arrive.shared.b64 _, [%0];" :: "r"(mb) : "memory")
__device__ __forceinline__ void mb_wait(uint32_t mb, uint32_t parity) {
    asm volatile(
        "{\n .reg .pred P;\n"
        "W%=:\n"
        " mbarrier.try_wait.parity.acquire.cta.shared::cta.b64 P, [%0], %1, 0x989680;\n"
        " @P bra D%=;\n"
        " bra W%=;\n"
        "D%=:\n}"
        :: "r"(mb), "r"(parity) : "memory");
}
__device__ __forceinline__ void bulkcp(uint32_t dst, const void* src, uint32_t bytes, uint32_t mbar) {
    asm volatile(
        "cp.async.bulk.shared::cluster.global.mbarrier::complete_tx::bytes [%0], [%1], %2, [%3];"
        :: "r"(dst), "l"(src), "r"(bytes), "r"(mbar) : "memory");
}
#define BAR_PAIR(id) \
    asm volatile("bar.sync %0, 64;" :: "r"(id) : "memory")

// ====================================================================
// W prep (unchanged).
// ====================================================================
__global__ void __launch_bounds__(512) wprep(
    const float* __restrict__ wv, const float* __restrict__ wq,
    const float* __restrict__ wk)
{
    const int dt = blockIdx.x;
    const int tid = threadIdx.x;
    const int kc = tid >> 5, ln = tid & 31;
    const int l4 = ln >> 2, t = ln & 3;

    const float* W;
    int rbase;
    float scale = 1.0f;
    if (dt < 16)      { W = wv; rbase = dt * 16; }
    else if (dt < 18) { W = wq; rbase = (dt - 16) * 16; scale = LOG2E; }
    else              { W = wk; rbase = (dt - 18) * 16; }

    const int r0 = rbase + l4, r1 = r0 + 8;
    const int c0 = kc * 16 + 2 * t;
    float f[8];
    f[0] = W[r0 * 256 + c0]     * scale;  f[1] = W[r0 * 256 + c0 + 1] * scale;
    f[2] = W[r1 * 256 + c0]     * scale;  f[3] = W[r1 * 256 + c0 + 1] * scale;
    f[4] = W[r0 * 256 + c0 + 8] * scale;  f[5] = W[r0 * 256 + c0 + 9] * scale;
    f[6] = W[r1 * 256 + c0 + 8] * scale;  f[7] = W[r1 * 256 + c0 + 9] * scale;

    __half h[8]; float l[8];
#pragma unroll
    for (int i = 0; i < 8; i++) {
        h[i] = __float2half_rn(f[i]);
        l[i] = f[i] - __half2float(h[i]);
    }
    uint4 hiw, low;
    hiw.x = pack2h(h[1], h[0]); hiw.y = pack2h(h[3], h[2]);
    hiw.z = pack2h(h[5], h[4]); hiw.w = pack2h(h[7], h[6]);
    low.x = packh2(l[1], l[0]); low.y = packh2(l[3], l[2]);
    low.z = packh2(l[5], l[4]); low.w = packh2(l[7], l[6]);
    uint4* dst = (uint4*)g_wA + (dt * 512 + kc * 32 + ln);
    dst[0]     = hiw;
    dst[10240] = low;
}

// ====================================================================
// proj_mma (round-13 monolithic structure; V warps skip 3rd pass).
// ====================================================================
#define RAW_STRIDE 68
#define SM_RAW  0
#define SM_FRAG 17408   /* floats */
#define PROJ2_SMEM_BYTES ((17408 + 16384) * 4)

__global__ void __launch_bounds__(640, 1) proj_mma(
    const float* __restrict__ x,
    const float* __restrict__ bq, const float* __restrict__ bk,
    const float* __restrict__ bv)
{
    extern __shared__ float sm[];
    const int tid = threadIdx.x;
    const int b  = blockIdx.y;
    const int bx = blockIdx.x;
    const int w  = tid >> 5, l = tid & 31;
    const int l4 = l >> 2, t = l & 3;

    // ---- phase 0: x -> raw[c][RAW_STRIDE] ----
    {
        const float4* xg = (const float4*)(x + ((size_t)b * C_) * N_ + bx * 64);
        for (int idx = tid; idx < 4096; idx += 640) {
            int c = idx >> 4, nI = idx & 15;
            float4 v = xg[(size_t)c * (N_ / 4) + nI];
            *(float4*)(sm + SM_RAW + c * RAW_STRIDE + nI * 4) = v;
        }
    }
    __syncthreads();
    // ---- phase 1: fp32 -> fp16 hi/lo B fragments ----
    for (int idx = tid; idx < 4096; idx += 640) {
        int kc = idx >> 8, nf = (idx >> 5) & 7, ln = idx & 31;
        int l4p = ln >> 2, tp = ln & 3;
        int n = nf * 8 + l4p, c = kc * 16 + 2 * tp;
        const float* rp = sm + SM_RAW + n;
        float f0 = rp[c * RAW_STRIDE];
        float f1 = rp[(c + 1) * RAW_STRIDE];
        float f2 = rp[(c + 8) * RAW_STRIDE];
        float f3 = rp[(c + 9) * RAW_STRIDE];
        __half h0 = __float2half_rn(f0), h1 = __float2half_rn(f1);
        __half h2 = __float2half_rn(f2), h3 = __float2half_rn(f3);
        uint4 o;
        o.x = pack2h(h1, h0);
        o.y = pack2h(h3, h2);
        o.z = packh2(f1 - __half2float(h1), f0 - __half2float(h0));
        o.w = packh2(f3 - __half2float(h3), f2 - __half2float(h2));
        *(uint4*)(sm + SM_FRAG + ((kc * 8 + nf) * 32 + ln) * 4) = o;
    }
    __syncthreads();

    // ---- phase 2: MMA, warp w = d-tile ----
    float acc[8][4];
#pragma unroll
    for (int i = 0; i < 8; i++)
#pragma unroll
        for (int e = 0; e < 4; e++) acc[i][e] = 0.f;

    const uint4* wAhi = (const uint4*)g_wA + (w * 512 + l);
    const bool qk = (w >= 16);
    for (int kc = 0; kc < 16; kc++) {
        uint4 ah = __ldg(wAhi + kc * 32);
        uint4 al = __ldg(wAhi + kc * 32 + 10240);
        const uint4* fb = (const uint4*)(sm + SM_FRAG) + (kc * 8) * 32 + l;
#pragma unroll
        for (int nf = 0; nf < 8; nf++) {
            uint4 xb = fb[nf * 32];
            mma_f16(acc[nf], ah.x, ah.y, ah.z, ah.w, xb.x, xb.y);
            mma_f16(acc[nf], al.x, al.y, al.z, al.w, xb.x, xb.y);
            if (qk)            // V skips 3rd pass (stored fp16 anyway)
                mma_f16(acc[nf], ah.x, ah.y, ah.z, ah.w, xb.z, xb.w);
        }
    }

    // ---- phase 3: scatter to attn layouts (verbatim r13) ----
    if (w < 16) {
        const float bv0 = __ldg(bv + w * 16 + l4);
        const float bv1 = __ldg(bv + w * 16 + l4 + 8);
        __half* vout = g_v + (((size_t)(b * 64 + bx)) << 14) + w * 256 + l4 * 32 + t * 8;
#pragma unroll
        for (int u = 0; u < 4; u++) {
            const int nA = 2 * u, nB = 2 * u + 1;
            uint4 o;
            o.x = packh2(acc[nA][1] + bv0, acc[nA][0] + bv0);
            o.y = packh2(acc[nB][1] + bv0, acc[nB][0] + bv0);
            o.z = packh2(acc[nA][3] + bv1, acc[nA][2] + bv1);
            o.w = packh2(acc[nB][3] + bv1, acc[nB][2] + bv1);
            *(uint4*)(vout + u * 4096) = o;
        }
    } else {
        float* stg = sm + SM_RAW + (w - 16) * 1100;
#pragma unroll
        for (int nf = 0; nf < 8; nf++) {
            stg[l4 * RAW_STRIDE + nf * 8 + 2 * t]           = acc[nf][0];
            stg[l4 * RAW_STRIDE + nf * 8 + 2 * t + 1]       = acc[nf][1];
            stg[(l4 + 8) * RAW_STRIDE + nf * 8 + 2 * t]     = acc[nf][2];
            stg[(l4 + 8) * RAW_STRIDE + nf * 8 + 2 * t + 1] = acc[nf][3];
        }
        __syncwarp();
        const int kg  = (w - 16) & 1;
        const bool isQ = (w < 18);
        const float* bias = isQ ? bq : bk;
        const float bsc = isQ ? LOG2E : 1.0f;
        __half *outh, *outl;
        if (isQ) {
            outh = g_q + (((size_t)(b * 32 + (bx >> 1))) << 13) + kg * 2048;
            outl = outh + 4096;
        } else {
            outh = g_k + (((size_t)(b * 64 + bx)) << 12);
            outl = outh + 2048;
        }
#pragma unroll
        for (int i = 0; i < 8; i++) {
            const int tidx = i * 32 + l;
            const int n = tidx >> 2, tt = tidx & 3;
            const int d0 = kg * 16 + 2 * tt;
            float f0 = stg[(2 * tt) * RAW_STRIDE + n]     + bsc * __ldg(bias + d0);
            float f1 = stg[(2 * tt + 1) * RAW_STRIDE + n] + bsc * __ldg(bias + d0 + 1);
            float f2 = stg[(2 * tt + 8) * RAW_STRIDE + n] + bsc * __ldg(bias + d0 + 8);
            float f3 = stg[(2 * tt + 9) * RAW_STRIDE + n] + bsc * __ldg(bias + d0 + 9);
            __half h0 = __float2half_rn(f0), h1 = __float2half_rn(f1);
            __half h2 = __float2half_rn(f2), h3 = __float2half_rn(f3);
            uint2 hw, lw;
            hw.x = pack2h(h1, h0);
            hw.y = pack2h(h3, h2);
            lw.x = packh2(f1 - __half2float(h1), f0 - __half2float(h0));
            lw.y = packh2(f3 - __half2float(h3), f2 - __half2float(h2));
            uint32_t off;
            if (isQ) {
                const int r = (bx & 1) * 64 + n;
                off = (uint32_t)((r >> 4) * 256 + (r & 7) * 32 + tt * 8 + ((r >> 3) & 1) * 4);
            } else {
                off = (uint32_t)((n >> 3) * 256 + (n & 7) * 32 + tt * 8 + kg * 4);
            }
            *(uint2*)(outh + off) = hw;
            *(uint2*)(outl + off) = lw;
        }
    }
}

// ====================================================================
// fp16 flash attention (UNCHANGED from round 13).
// ====================================================================
#define SM_BUF   0
#define BUF_SZ   40960
#define SM_PSH   163840
#define SM_F     196608
#define SM_MX    197632
#define SM_LS    198656
#define SM_LS2   199680
#define SM_MBAR  200192
#define ATTN_SMEM_BYTES 200448

__global__ void __launch_bounds__(512, 1) attn_mma(
    const float* __restrict__ x, float* __restrict__ out)
{
    extern __shared__ float sm[];
    const uint32_t sb = su32(sm);
    const int tid = threadIdx.x;
    const int w   = tid >> 5;
    const int qw  = w & 7;
    const int cg  = w >> 3;
    const int qp  = w & 3;
    const int ch  = w >> 2;
    const int l   = tid & 31;
    const int l4  = l >> 2;
    const int t   = l & 3;
    const int b   = blockIdx.y;
    const int qt  = blockIdx.x;
    const int q0  = qt * TQ;
    const uint32_t lane16 = (uint32_t)l * 16;
    const int barid = 1 + qw;

    const uint32_t mbD = sb + SM_MBAR;
    const uint32_t mbC = sb + SM_MBAR + 32;
    const uint32_t mxO = sb + SM_MX + (uint32_t)(((qw * 2 + cg) * 8 + l4) * 8);
    const uint32_t mxP = sb + SM_MX + (uint32_t)(((qw * 2 + (1 - cg)) * 8 + l4) * 8);

    if (tid == 0) {
#pragma unroll
        for (int i = 0; i < 4; i++) { MB_INIT(mbD + 8 * i, 1); MB_INIT(mbC + 8 * i, 16); }
    }
    __syncthreads();

    if (tid == 0) {
#pragma unroll
        for (int i = 0; i < 4; i++) {
            MB_EXPECT(mbD + 8 * i, 40960);
            bulkcp(sb + SM_BUF + i * BUF_SZ,
                   (const char*)g_k + ((size_t)(b * 64 + i) << 13), 8192, mbD + 8 * i);
            bulkcp(sb + SM_BUF + i * BUF_SZ + 8192,
                   (const char*)g_v + ((size_t)(b * 64 + i) << 15), 32768, mbD + 8 * i);
        }
    }

    uint32_t qh[2][4], ql[2][4];
    {
        const __half* qgm = g_q + ((size_t)(b * 32 + qt) << 13);
#pragma unroll
        for (int kg = 0; kg < 2; kg++) {
            uint4 v = *(const uint4*)(qgm + kg * 2048 + qw * 256 + l * 8);
            qh[kg][0] = v.x; qh[kg][1] = v.z; qh[kg][2] = v.y; qh[kg][3] = v.w;
            uint4 u2 = *(const uint4*)(qgm + 4096 + kg * 2048 + qw * 256 + l * 8);
            ql[kg][0] = u2.x; ql[kg][1] = u2.z; ql[kg][2] = u2.y; ql[kg][3] = u2.w;
        }
    }

    float o[16][4];
#pragma unroll
    for (int i = 0; i < 16; i++)
#pragma unroll
        for (int e = 0; e < 4; e++) o[i][e] = 0.f;
    float m0 = -1e30f, m1 = -1e30f, ls0 = 0.f, ls1 = 0.f;

    for (int tt = 0; tt < NT; tt++) {
        const int buf = tt & 3;
        const uint32_t kb = sb + SM_BUF + (uint32_t)buf * BUF_SZ;
        const uint32_t vb = kb + 8192;
        const uint32_t par = (uint32_t)((tt >> 2) & 1);
        const uint32_t pshB = sb + SM_PSH + (uint32_t)(tt & 1) * 16384;
        const uint32_t fB   = sb + SM_F   + (uint32_t)(tt & 1) * 512;
        mb_wait(mbD + 8 * buf, par);

        float sacc[4][4];
        const uint32_t kaBase = kb + (uint32_t)(cg * 2048) + lane16;
#pragma unroll
        for (int nt = 0; nt < 4; nt++) {
#pragma unroll
            for (int e = 0; e < 4; e++) sacc[nt][e] = 0.f;
            const uint32_t ka = kaBase + (uint32_t)(nt * 512);
            uint32_t h0, h1, h2, h3, g0, g1, g2, g3;
            lds128(h0, h1, h2, h3, ka);
            lds128(g0, g1, g2, g3, ka + 4096);
            mma_f16(sacc[nt], qh[0][0], qh[0][1], qh[0][2], qh[0][3], h0, h1);
            mma_f16(sacc[nt], qh[1][0], qh[1][1], qh[1][2], qh[1][3], h2, h3);
            mma_f16(sacc[nt], ql[0][0], ql[0][1], ql[0][2], ql[0][3], h0, h1);
            mma_f16(sacc[nt], ql[1][0], ql[1][1], ql[1][2], ql[1][3], h2, h3);
            mma_f16(sacc[nt], qh[0][0], qh[0][1], qh[0][2], qh[0][3], g0, g1);
            mma_f16(sacc[nt], qh[1][0], qh[1][1], qh[1][2], qh[1][3], g2, g3);
        }
        float mh0 = sacc[0][0], mh1 = sacc[0][2];
#pragma unroll
        for (int nt = 0; nt < 4; nt++) {
            mh0 = fmaxf(mh0, fmaxf(sacc[nt][0], sacc[nt][1]));
            mh1 = fmaxf(mh1, fmaxf(sacc[nt][2], sacc[nt][3]));
        }
        mh0 = fmaxf(mh0, __shfl_xor_sync(0xffffffffu, mh0, 1));
        mh0 = fmaxf(mh0, __shfl_xor_sync(0xffffffffu, mh0, 2));
        mh1 = fmaxf(mh1, __shfl_xor_sync(0xffffffffu, mh1, 1));
        mh1 = fmaxf(mh1, __shfl_xor_sync(0xffffffffu, mh1, 2));
        if (t == 0) sts_f2(mxO, mh0, mh1);
        BAR_PAIR(barid);
        float pm0, pm1;
        lds_f2(pm0, pm1, mxP);
        const float m0n = fmaxf(m0, fmaxf(mh0, pm0));
        const float m1n = fmaxf(m1, fmaxf(mh1, pm1));
        const float f0 = ex2f(m0 - m0n);
        const float f1 = ex2f(m1 - m1n);
        m0 = m0n; m1 = m1n;
        ls0 *= f0; ls1 *= f1;
        if (cg == 0 && t == 0) sts_f2(fB + (uint32_t)(qw * 64 + l4 * 8), f0, f1);

#pragma unroll
        for (int ul = 0; ul < 2; ul++) {
            const int u = cg * 2 + ul;
            uint32_t A0, A1, A2, A3;
            {
                float p0 = ex2f(sacc[2 * ul][0] - m0), p1 = ex2f(sacc[2 * ul][1] - m0);
                float p2 = ex2f(sacc[2 * ul][2] - m1), p3 = ex2f(sacc[2 * ul][3] - m1);
                A0 = packh2(p1, p0); A1 = packh2(p3, p2);
                p0 = ex2f(sacc[2 * ul + 1][0] - m0); p1 = ex2f(sacc[2 * ul + 1][1] - m0);
                p2 = ex2f(sacc[2 * ul + 1][2] - m1); p3 = ex2f(sacc[2 * ul + 1][3] - m1);
                A2 = packh2(p1, p0); A3 = packh2(p3, p2);
                ls0 += h2sum(A0) + h2sum(A2);
                ls1 += h2sum(A1) + h2sum(A3);
            }
            sts128(pshB + (uint32_t)(qw * 2048 + u * 512) + lane16, A0, A1, A2, A3);
        }
        __syncthreads();

        {
            float g0a, g1a, g0b, g1b;
            lds_f2(g0a, g1a, fB + (uint32_t)((2 * qp) * 64 + l4 * 8));
            lds_f2(g0b, g1b, fB + (uint32_t)((2 * qp + 1) * 64 + l4 * 8));
#pragma unroll
            for (int i = 0; i < 8; i++) {
                o[i][0] *= g0a; o[i][1] *= g0a; o[i][2] *= g1a; o[i][3] *= g1a;
            }
#pragma unroll
            for (int i = 8; i < 16; i++) {
                o[i][0] *= g0b; o[i][1] *= g0b; o[i][2] *= g1b; o[i][3] *= g1b;
            }
        }
#pragma unroll
        for (int u = 0; u < 4; u++) {
            uint32_t A0, A1, A2, A3, B0, B1, B2, B3;
            lds128(A0, A1, A2, A3, pshB + (uint32_t)((2 * qp) * 2048 + u * 512) + lane16);
            lds128(B0, B1, B2, B3, pshB + (uint32_t)((2 * qp + 1) * 2048 + u * 512) + lane16);
            uint32_t va = vb + (uint32_t)(u * 8192 + ch * 2048) + lane16;
#pragma unroll
            for (int p = 0; p < 4; p++) {
                uint32_t v0, v1, v2, v3;
                lds128(v0, v1, v2, v3, va);
                mma_f16(o[p * 2],         A0, A1, A2, A3, v0, v1);
                mma_f16(o[p * 2 + 1],     A0, A1, A2, A3, v2, v3);
                mma_f16(o[8 + p * 2],     B0, B1, B2, B3, v0, v1);
                mma_f16(o[8 + p * 2 + 1], B0, B1, B2, B3, v2, v3);
                va += 512;
            }
        }
        if (l == 0) MB_ARRIVE(mbC + 8 * buf);
        if (tid == 0 && tt + 4 < NT) {
            mb_wait(mbC + 8 * buf, par);
            MB_EXPECT(mbD + 8 * buf, 40960);
            bulkcp(kb, (const char*)g_k + ((size_t)(b * 64 + tt + 4) << 13), 8192, mbD + 8 * buf);
            bulkcp(vb, (const char*)g_v + ((size_t)(b * 64 + tt + 4) << 15), 32768, mbD + 8 * buf);
        }
    }

    ls0 += __shfl_xor_sync(0xffffffffu, ls0, 1);
    ls0 += __shfl_xor_sync(0xffffffffu, ls0, 2);
    ls1 += __shfl_xor_sync(0xffffffffu, ls1, 1);
    ls1 += __shfl_xor_sync(0xffffffffu, ls1, 2);
    if (t == 0) sts_f2(sb + SM_LS + (uint32_t)(((qw * 2 + cg) * 8 + l4) * 8), ls0, ls1);
    __syncthreads();
    {
        float p0, p1;
        lds_f2(p0, p1, sb + SM_LS + (uint32_t)(((qw * 2 + (1 - cg)) * 8 + l4) * 8));
        ls0 += p0; ls1 += p1;
    }
    if (cg == 0 && t == 0) {
        sm[(SM_LS2 >> 2) + qw * 16 + l4]     = ls0;
        sm[(SM_LS2 >> 2) + qw * 16 + l4 + 8] = ls1;
    }
    __syncthreads();
    float inv0a, inv1a, inv0b, inv1b;
    {
        const float* lsf = sm + (SM_LS2 >> 2);
        inv0a = 1.0f / lsf[(2 * qp) * 16 + l4];
        inv1a = 1.0f / lsf[(2 * qp) * 16 + l4 + 8];
        inv0b = 1.0f / lsf[(2 * qp + 1) * 16 + l4];
        inv1b = 1.0f / lsf[(2 * qp + 1) * 16 + l4 + 8];
    }

    float* stage = sm;
#pragma unroll 1
    for (int ch2 = 0; ch2 < 4; ch2++) {
        __syncthreads();
        if (ch == ch2) {
#pragma unroll
            for (int qb = 0; qb < 2; qb++) {
                const int q = (2 * qp + qb) * 16 + l4;
                const float i0 = qb ? inv0b : inv0a;
                const float i1 = qb ? inv1b : inv1a;
#pragma unroll
                for (int k = 0; k < 8; k++) {
                    const int i = qb * 8 + k;
                    const int cloc = k * 8 + 2 * t;
                    stage[cloc * 132 + q]           = o[i][0] * i0;
                    stage[(cloc + 1) * 132 + q]     = o[i][1] * i0;
                    stage[cloc * 132 + q + 8]       = o[i][2] * i1;
                    stage[(cloc + 1) * 132 + q + 8] = o[i][3] * i1;
                }
            }
        }
        __syncthreads();
        const int cloc2 = tid & 63;
        const int seg   = tid >> 6;
        const int cglob = ch2 * 64 + cloc2;
        const size_t gbase = ((size_t)(b * C_ + cglob)) * N_ + q0 + seg * 16;
        const float4* xs4 = (const float4*)(x + gbase);
        float4* os4 = (float4*)(out + gbase);
        const float* srow = stage + cloc2 * 132 + seg * 16;
#pragma unroll
        for (int i = 0; i < 4; i++) {
            float4 v = *(const float4*)(srow + 4 * i);
            float4 xv = xs4[i];
            float4 r;
            r.x = xv.x + v.x; r.y = xv.y + v.y; r.z = xv.z + v.z; r.w = xv.w + v.w;
            os4[i] = r;
        }
    }
}

// ====================================================================
extern "C" void kernel_launch(void* const* d_in, const int* in_sizes, int n_in,
                              void* d_out, int out_size)
{
    const float* x  = (const float*)d_in[0];
    const float* wq = (const float*)d_in[1];
    const float* bq = (const float*)d_in[2];
    const float* wk = (const float*)d_in[3];
    const float* bk = (const float*)d_in[4];
    const float* wv = (const float*)d_in[5];
    const float* bv = (const float*)d_in[6];
    float* out = (float*)d_out;

    cudaFuncSetAttribute(proj_mma, cudaFuncAttributeMaxDynamicSharedMemorySize, PROJ2_SMEM_BYTES);
    cudaFuncSetAttribute(attn_mma, cudaFuncAttributeMaxDynamicSharedMemorySize, ATTN_SMEM_BYTES);

    wprep<<<20, 512>>>(wv, wq, wk);
    proj_mma<<<dim3(64, 8), 640, PROJ2_SMEM_BYTES>>>(x, bq, bk, bv);
    attn_mma<<<dim3(N_ / TQ, B_), 512, ATTN_SMEM_BYTES>>>(x, out);
}